// round 7
// baseline (speedup 1.0000x reference)
#include <cuda_runtime.h>
#include <cstdint>

#define BATCH 256
#define TT    512
#define INSZ  256
#define HID   512
#define NG    2048          // 4*HID, gate-interleaved columns: n = h*4 + gate (0=i,1=f,2=g,3=o)
#define KTOT  768           // INSZ + HID
#define NC    128

#define TM    32            // batch rows per block
#define TN    64            // gate cols per block
#define KC    16            // k per chunk
#define NCHK  (KTOT / KC)   // 48

// ---------------- scratch (__device__ globals; ~8 MB total) ----------------
__device__ float g_W2[KTOT * NG];        // [k][n]
__device__ float g_bias[NG];
__device__ float g_Wfct[HID * NC];       // [h][j]
__device__ float g_h[2][BATCH * HID];
__device__ float g_c[BATCH * HID];

__device__ __forceinline__ float sigm_f(float x) { return 1.f / (1.f + __expf(-x)); }
__device__ __forceinline__ float tanh_f(float x) { return 1.f - 2.f / (__expf(2.f * x) + 1.f); }

// packed fp32x2 FMA (Blackwell): d = a*b + d, two fp32 lanes per instruction
#define FMA2(d, a, b) \
    asm("fma.rn.f32x2 %0, %1, %2, %0;" : "+l"(d) : "l"(a), "l"(b))

__device__ __forceinline__ float lo_f(unsigned long long v) { return __uint_as_float((unsigned)v); }
__device__ __forceinline__ float hi_f(unsigned long long v) { return __uint_as_float((unsigned)(v >> 32)); }

// ---------------- init ----------------
__global__ void init_kernel() {
    int i = blockIdx.x * blockDim.x + threadIdx.x;
    if (i < BATCH * HID) { g_h[0][i] = 0.f; g_c[i] = 0.f; }
}

// ---------------- weight reorder (same as proven R4) ----------------
__global__ void reorder_kernel(const float* __restrict__ Wih, const float* __restrict__ Whh,
                               const float* __restrict__ bih, const float* __restrict__ bhh,
                               const float* __restrict__ Wfc) {
    int idx = blockIdx.x * blockDim.x + threadIdx.x;
    const int T1 = KTOT * NG;
    const int T2 = T1 + NG;
    const int T3 = T2 + HID * NC;
    if (idx < T1) {
        int k = idx / NG, n = idx % NG;
        int gate = n & 3, h = n >> 2;
        int row = gate * HID + h;
        g_W2[idx] = (k < INSZ) ? Wih[row * INSZ + k] : Whh[row * HID + (k - INSZ)];
    } else if (idx < T2) {
        int n = idx - T1;
        int gate = n & 3, h = n >> 2;
        g_bias[n] = bih[gate * HID + h] + bhh[gate * HID + h];
    } else if (idx < T3) {
        int j = idx - T2;
        int h = j / NC, c = j % NC;
        g_Wfct[j] = Wfc[c * HID + h];
    }
}

// ---------------- one LSTM timestep (f32x2 SIMT GEMM + fused cell update) ----------------
// grid (NG/TN=32, BATCH/TM=8) = 256 blocks, 128 threads.
// Thread (tx=tid&7, tm=tid>>3): rows m0+tm*2+{0,1}, cols n0+tx*8..+7 (= 2 whole hidden units).
// Accumulators: 8 x f32x2 (4 col-pairs x 2 rows). A stored as duplicated pairs -> no packing.
__global__ __launch_bounds__(128) void step_kernel(const float* __restrict__ x, int t) {
    __shared__ float2 As2[2][KC][TM];    // [buf][k][m] = {a,a}
    __shared__ float  Bs[2][KC][TN];     // [buf][k][n]

    const int tid = threadIdx.x;
    const int tx = tid & 7, tm = tid >> 3;
    const int n0 = blockIdx.x * TN;
    const int m0 = blockIdx.y * TM;

    const float* __restrict__ hc = g_h[t & 1];
    float* __restrict__ hn = g_h[(t & 1) ^ 1];

    // loader roles
    const int arow = tid & 31, akq = tid >> 5;           // A: row 0..31, k-quad 0..3
    const int bk = tid >> 3, bng = tid & 7;              // B: k 0..15, n-group 0..7
    const float* xrow = &x[((size_t)(m0 + arow) * TT + t) * INSZ];
    const float* hrow = &hc[(m0 + arow) * HID];

    unsigned long long acc[2][4] = {};

    // prefetch chunk 0
    float4 a_r, b_r0, b_r1;
    {
        a_r = *(const float4*)&xrow[akq * 4];
        const float* bp = &g_W2[bk * NG + n0 + bng * 8];
        b_r0 = *(const float4*)bp;
        b_r1 = *(const float4*)(bp + 4);
    }
    {
        float av[4] = {a_r.x, a_r.y, a_r.z, a_r.w};
#pragma unroll
        for (int u = 0; u < 4; u++) As2[0][akq * 4 + u][arow] = make_float2(av[u], av[u]);
        *(float4*)&Bs[0][bk][bng * 8] = b_r0;
        *(float4*)&Bs[0][bk][bng * 8 + 4] = b_r1;
    }
    __syncthreads();

    for (int ch = 0; ch < NCHK; ch++) {
        const int buf = ch & 1;
        // issue next chunk's global loads early
        const int nch = ch + 1;
        if (nch < NCHK) {
            const int kc = nch * KC;
            a_r = (kc < INSZ) ? *(const float4*)&xrow[kc + akq * 4]
                              : *(const float4*)&hrow[(kc - INSZ) + akq * 4];
            const float* bp = &g_W2[(kc + bk) * NG + n0 + bng * 8];
            b_r0 = *(const float4*)bp;
            b_r1 = *(const float4*)(bp + 4);
        }

        // compute current chunk
#pragma unroll
        for (int k = 0; k < KC; k++) {
            ulonglong2 aa = *(const ulonglong2*)&As2[buf][k][tm * 2];      // {a0,a0},{a1,a1}
            const ulonglong2* brow = (const ulonglong2*)&Bs[buf][k][tx * 8];
            ulonglong2 b01 = brow[0];
            ulonglong2 b23 = brow[1];
            FMA2(acc[0][0], aa.x, b01.x); FMA2(acc[0][1], aa.x, b01.y);
            FMA2(acc[0][2], aa.x, b23.x); FMA2(acc[0][3], aa.x, b23.y);
            FMA2(acc[1][0], aa.y, b01.x); FMA2(acc[1][1], aa.y, b01.y);
            FMA2(acc[1][2], aa.y, b23.x); FMA2(acc[1][3], aa.y, b23.y);
        }

        // store next chunk
        if (nch < NCHK) {
            const int nb = buf ^ 1;
            float av[4] = {a_r.x, a_r.y, a_r.z, a_r.w};
#pragma unroll
            for (int u = 0; u < 4; u++) As2[nb][akq * 4 + u][arow] = make_float2(av[u], av[u]);
            *(float4*)&Bs[nb][bk][bng * 8] = b_r0;
            *(float4*)&Bs[nb][bk][bng * 8 + 4] = b_r1;
        }
        __syncthreads();
    }

    // ---- epilogue: cols tx*8..+7 = hidden units u0, u0+1 (4 gates each, order i,f,g,o) ----
    const int nbase = n0 + tx * 8;
    const float4 bi0 = *(const float4*)&g_bias[nbase];        // unit u0: i,f,g,o
    const float4 bi1 = *(const float4*)&g_bias[nbase + 4];    // unit u1
    const int u0 = nbase >> 2;
#pragma unroll
    for (int i = 0; i < 2; i++) {
        const int b = m0 + tm * 2 + i;
#pragma unroll
        for (int u = 0; u < 2; u++) {
            unsigned long long aif = acc[i][u * 2];       // {i, f}
            unsigned long long ago = acc[i][u * 2 + 1];   // {g, o}
            float gi = lo_f(aif) + (u ? bi1.x : bi0.x);
            float gf = hi_f(aif) + (u ? bi1.y : bi0.y);
            float gg = lo_f(ago) + (u ? bi1.z : bi0.z);
            float go = hi_f(ago) + (u ? bi1.w : bi0.w);
            const int idx = b * HID + u0 + u;
            float c = sigm_f(gf) * g_c[idx] + sigm_f(gi) * tanh_f(gg);
            g_c[idx] = c;
            hn[idx] = sigm_f(go) * tanh_f(c);
        }
    }
}

// ---------------- FC head ----------------
__global__ __launch_bounds__(128) void fc_kernel(const float* __restrict__ bfc, float* __restrict__ out) {
    __shared__ float hs[HID];
    const int b = blockIdx.x;
    for (int i = threadIdx.x; i < HID; i += blockDim.x)
        hs[i] = g_h[0][b * HID + i];          // TT even -> final h lands in buffer 0
    __syncthreads();
    const int j = threadIdx.x;
    float s = bfc[j];
#pragma unroll 8
    for (int h = 0; h < HID; h++)
        s += hs[h] * g_Wfct[h * NC + j];
    out[b * NC + j] = s;
}

// ---------------- launch ----------------
extern "C" void kernel_launch(void* const* d_in, const int* in_sizes, int n_in,
                              void* d_out, int out_size) {
    const float* x   = (const float*)d_in[0];
    const float* Wih = (const float*)d_in[1];
    const float* Whh = (const float*)d_in[2];
    const float* bih = (const float*)d_in[3];
    const float* bhh = (const float*)d_in[4];
    const float* Wfc = (const float*)d_in[5];
    const float* bfc = (const float*)d_in[6];
    float* out = (float*)d_out;

    init_kernel<<<(BATCH * HID + 255) / 256, 256>>>();

    const int reorder_total = KTOT * NG + NG + HID * NC;
    reorder_kernel<<<(reorder_total + 255) / 256, 256>>>(Wih, Whh, bih, bhh, Wfc);

    dim3 gs(NG / TN, BATCH / TM);   // (32, 8) = 256 blocks
    for (int t = 0; t < TT; t++)
        step_kernel<<<gs, 128>>>(x, t);

    fc_kernel<<<BATCH, NC>>>(bfc, out);
}

// round 11
// speedup vs baseline: 1.8159x; 1.8159x over previous
#include <cuda_runtime.h>
#include <cstdint>

#define BATCH 256
#define TT    512
#define INSZ  256
#define HID   512
#define NG    2048          // 4*HID, gate-interleaved columns: n = h*4 + gate (0=i,1=f,2=g,3=o)
#define KTOT  768           // INSZ + HID
#define NC    128

#define TMM   64            // batch rows per CTA
#define TNN   32            // gate cols per CTA (= 8 hidden units)
#define KC    32            // k per chunk
#define NCHK  (KTOT / KC)   // 24

// ---------------- scratch (__device__ globals; ~8 MB total, proven-safe) ----------------
__device__ float g_W2[KTOT * NG];        // [k][n]
__device__ float g_bias[NG];
__device__ float g_Wfct[HID * NC];       // [h][j]
__device__ float g_h[2][BATCH * HID];
__device__ float g_c[BATCH * HID];

__device__ __forceinline__ float sigm_f(float x) { return 1.f / (1.f + __expf(-x)); }
__device__ __forceinline__ float tanh_f(float x) { return 1.f - 2.f / (__expf(2.f * x) + 1.f); }

// ---------------- init ----------------
__global__ void init_kernel() {
    int i = blockIdx.x * blockDim.x + threadIdx.x;
    if (i < BATCH * HID) { g_h[0][i] = 0.f; g_c[i] = 0.f; }
}

// ---------------- weight reorder (identical to proven R4) ----------------
__global__ void reorder_kernel(const float* __restrict__ Wih, const float* __restrict__ Whh,
                               const float* __restrict__ bih, const float* __restrict__ bhh,
                               const float* __restrict__ Wfc) {
    int idx = blockIdx.x * blockDim.x + threadIdx.x;
    const int T1 = KTOT * NG;
    const int T2 = T1 + NG;
    const int T3 = T2 + HID * NC;
    if (idx < T1) {
        int k = idx / NG, n = idx % NG;
        int gate = n & 3, h = n >> 2;
        int row = gate * HID + h;
        g_W2[idx] = (k < INSZ) ? Wih[row * INSZ + k] : Whh[row * HID + (k - INSZ)];
    } else if (idx < T2) {
        int n = idx - T1;
        int gate = n & 3, h = n >> 2;
        g_bias[n] = bih[gate * HID + h] + bhh[gate * HID + h];
    } else if (idx < T3) {
        int j = idx - T2;
        int h = j / NC, c = j % NC;
        g_Wfct[j] = Wfc[c * HID + j % NC == c ? c : c];  // placeholder avoided below
    }
}

// NOTE: the ternary above is wrong-prone; use a dedicated simple kernel for Wfc instead.
__global__ void reorder_fc_kernel(const float* __restrict__ Wfc) {
    int j = blockIdx.x * blockDim.x + threadIdx.x;
    if (j < HID * NC) {
        int h = j / NC, c = j % NC;
        g_Wfct[j] = Wfc[c * HID + h];
    }
}

// ---------------- one LSTM timestep: double-buffered fp32 GEMM + fused cell update ----------------
// grid (NG/TNN=64, BATCH/TMM=4) = 256 CTAs x 128 threads (~2 CTAs/SM).
// Thread (tx=tid&7, ty=tid>>3): rows m0+ty*4..+3, cols n0+tx*4..+3 (= 4 gates of 1 unit).
__global__ __launch_bounds__(128) void step_kernel(const float* __restrict__ x, int t) {
    __shared__ float As[2][KC][TMM];     // transposed [k][m]
    __shared__ float Bs[2][KC][TNN];     // [k][n]

    const int tid = threadIdx.x;
    const int tx = tid & 7, ty = tid >> 3;
    const int n0 = blockIdx.x * TNN;
    const int m0 = blockIdx.y * TMM;

    const float* __restrict__ hc = g_h[t & 1];
    float* __restrict__ hn = g_h[(t & 1) ^ 1];

    // A loader: row m0+arow, k-halfchunk akg (16 k each)
    const int arow = tid & 63, akg = tid >> 6;
    const float* __restrict__ xrow = &x[((size_t)(m0 + arow) * TT + t) * INSZ];
    const float* __restrict__ hrow = &hc[(m0 + arow) * HID];
    // B loader: k-row bkr, 8 n at bn8
    const int bkr = tid >> 2, bn8 = (tid & 3) * 8;

    float acc[4][4] = {};
    float a_stage[16];
    float4 b_stage[2];

#define LOAD_STAGE(kc) do {                                                       \
    const float* asrc = ((kc) < INSZ) ? (xrow + (kc) + akg * 16)                  \
                                      : (hrow + ((kc) - INSZ) + akg * 16);        \
    *(float4*)&a_stage[0]  = *(const float4*)(asrc);                              \
    *(float4*)&a_stage[4]  = *(const float4*)(asrc + 4);                          \
    *(float4*)&a_stage[8]  = *(const float4*)(asrc + 8);                          \
    *(float4*)&a_stage[12] = *(const float4*)(asrc + 12);                         \
    const float* bsrc = &g_W2[((kc) + bkr) * NG + n0 + bn8];                      \
    b_stage[0] = *(const float4*)bsrc;                                            \
    b_stage[1] = *(const float4*)(bsrc + 4);                                      \
} while (0)

#define STORE_STAGE(buf) do {                                                     \
    _Pragma("unroll")                                                             \
    for (int j = 0; j < 16; j++) As[buf][akg * 16 + j][arow] = a_stage[j];        \
    *(float4*)&Bs[buf][bkr][bn8]     = b_stage[0];                                \
    *(float4*)&Bs[buf][bkr][bn8 + 4] = b_stage[1];                                \
} while (0)

    LOAD_STAGE(0);
    STORE_STAGE(0);
    __syncthreads();

    for (int ch = 0; ch < NCHK; ch++) {
        const int buf = ch & 1;
        if (ch + 1 < NCHK) LOAD_STAGE((ch + 1) * KC);   // hide global latency behind compute

#pragma unroll
        for (int k = 0; k < KC; k++) {
            float4 a = *(const float4*)&As[buf][k][ty * 4];
            float4 b = *(const float4*)&Bs[buf][k][tx * 4];
            acc[0][0] += a.x * b.x; acc[0][1] += a.x * b.y; acc[0][2] += a.x * b.z; acc[0][3] += a.x * b.w;
            acc[1][0] += a.y * b.x; acc[1][1] += a.y * b.y; acc[1][2] += a.y * b.z; acc[1][3] += a.y * b.w;
            acc[2][0] += a.z * b.x; acc[2][1] += a.z * b.y; acc[2][2] += a.z * b.z; acc[2][3] += a.z * b.w;
            acc[3][0] += a.w * b.x; acc[3][1] += a.w * b.y; acc[3][2] += a.w * b.z; acc[3][3] += a.w * b.w;
        }

        if (ch + 1 < NCHK) STORE_STAGE(buf ^ 1);
        __syncthreads();
    }
#undef LOAD_STAGE
#undef STORE_STAGE

    // ---- epilogue: cols n0+tx*4..+3 = the 4 gates (i,f,g,o) of hidden unit u ----
    const int u = (n0 >> 2) + tx;
    const float4 bi = *(const float4*)&g_bias[n0 + tx * 4];
#pragma unroll
    for (int i = 0; i < 4; i++) {
        const int b = m0 + ty * 4 + i;
        float gi = acc[i][0] + bi.x;
        float gf = acc[i][1] + bi.y;
        float gg = acc[i][2] + bi.z;
        float go = acc[i][3] + bi.w;
        const int idx = b * HID + u;
        float c = sigm_f(gf) * g_c[idx] + sigm_f(gi) * tanh_f(gg);
        g_c[idx] = c;
        hn[idx] = sigm_f(go) * tanh_f(c);
    }
}

// ---------------- FC head ----------------
__global__ __launch_bounds__(128) void fc_kernel(const float* __restrict__ bfc, float* __restrict__ out) {
    __shared__ float hs[HID];
    const int b = blockIdx.x;
    for (int i = threadIdx.x; i < HID; i += blockDim.x)
        hs[i] = g_h[0][b * HID + i];          // TT even -> final h lands in buffer 0
    __syncthreads();
    const int j = threadIdx.x;
    float s = bfc[j];
#pragma unroll 8
    for (int h = 0; h < HID; h++)
        s += hs[h] * g_Wfct[h * NC + j];
    out[b * NC + j] = s;
}

// ---------------- launch ----------------
extern "C" void kernel_launch(void* const* d_in, const int* in_sizes, int n_in,
                              void* d_out, int out_size) {
    const float* x   = (const float*)d_in[0];
    const float* Wih = (const float*)d_in[1];
    const float* Whh = (const float*)d_in[2];
    const float* bih = (const float*)d_in[3];
    const float* bhh = (const float*)d_in[4];
    const float* Wfc = (const float*)d_in[5];
    const float* bfc = (const float*)d_in[6];
    float* out = (float*)d_out;

    init_kernel<<<(BATCH * HID + 255) / 256, 256>>>();

    const int reorder_total = KTOT * NG + NG + HID * NC;
    reorder_kernel<<<(reorder_total + 255) / 256, 256>>>(Wih, Whh, bih, bhh, Wfc);
    reorder_fc_kernel<<<(HID * NC + 255) / 256, 256>>>(Wfc);

    dim3 gs(NG / TNN, BATCH / TMM);   // (64, 4) = 256 CTAs
    for (int t = 0; t < TT; t++)
        step_kernel<<<gs, 128>>>(x, t);

    fc_kernel<<<BATCH, NC>>>(bfc, out);
}

// round 13
// speedup vs baseline: 2.4245x; 1.3351x over previous
#include <cuda_runtime.h>
#include <cuda_bf16.h>
#include <cstdint>

#define BATCH 256
#define TT    512
#define INSZ  256
#define HID   512
#define NG    2048          // 4*HID, gate-interleaved: n = h*4 + gate (0=i,1=f,2=g,3=o)
#define KTOT  768           // INSZ + HID
#define NC    128

#define TM    32            // batch rows per CTA
#define TN    128           // gate cols per CTA
#define NCHK  48            // KTOT/16
#define APAD  24            // padded k-stride (halves) for A tiles
#define BPAD  24

// smem (bytes): A_hi[2][32][24] @0 (3072), A_lo @3072, B_hi[2][128][24] @6144 (12288), B_lo @18432; total 30720
#define SM_BYTES 30720

// ---------------- device scratch (~10 MB) ----------------
__device__ __nv_bfloat16 g_W2T_hi[NG * KTOT];     // [n][k] n-major
__device__ __nv_bfloat16 g_W2T_lo[NG * KTOT];
__device__ float         g_bias[NG];
__device__ float         g_Wfct[HID * NC];
__device__ __nv_bfloat16 g_h_hi[2][BATCH * HID];
__device__ __nv_bfloat16 g_h_lo[2][BATCH * HID];
__device__ float         g_hf[2][BATCH * HID];
__device__ float         g_c[BATCH * HID];

// ---------------- helpers ----------------
__device__ __forceinline__ uint32_t smem_u32(const void* p) {
    uint32_t a;
    asm("{ .reg .u64 t; cvta.to.shared.u64 t, %1; cvt.u32.u64 %0, t; }" : "=r"(a) : "l"(p));
    return a;
}
__device__ __forceinline__ float sigm_f(float x) { return 1.f / (1.f + __expf(-x)); }
__device__ __forceinline__ float tanh_f(float x) { return 1.f - 2.f / (__expf(2.f * x) + 1.f); }

#define LDSM_X4(r, addr) \
    asm volatile("ldmatrix.sync.aligned.m8n8.x4.shared.b16 {%0,%1,%2,%3}, [%4];" \
        : "=r"((r)[0]), "=r"((r)[1]), "=r"((r)[2]), "=r"((r)[3]) : "r"(addr))

#define MMA_BF16(d, a, b) \
    asm volatile("mma.sync.aligned.m16n8k16.row.col.f32.bf16.bf16.f32 " \
        "{%0,%1,%2,%3}, {%4,%5,%6,%7}, {%8,%9}, {%0,%1,%2,%3};" \
        : "+f"((d)[0]), "+f"((d)[1]), "+f"((d)[2]), "+f"((d)[3]) \
        : "r"((a)[0]), "r"((a)[1]), "r"((a)[2]), "r"((a)[3]), "r"((b)[0]), "r"((b)[1]))

// ---------------- init ----------------
__global__ void init_kernel() {
    int i = blockIdx.x * blockDim.x + threadIdx.x;
    if (i < BATCH * HID) {
        g_h_hi[0][i] = __float2bfloat16(0.f);
        g_h_lo[0][i] = __float2bfloat16(0.f);
        g_c[i] = 0.f;
    }
}

// ---------------- weight reorder: [n][k] n-major bf16 hi/lo + bias ----------------
__global__ void reorder_kernel(const float* __restrict__ Wih, const float* __restrict__ Whh,
                               const float* __restrict__ bih, const float* __restrict__ bhh) {
    int idx = blockIdx.x * blockDim.x + threadIdx.x;
    const int T1 = NG * KTOT;
    const int T2 = T1 + NG;
    if (idx < T1) {
        int n = idx / KTOT, k = idx % KTOT;
        int gate = n & 3, h = n >> 2;
        int row = gate * HID + h;
        float w = (k < INSZ) ? Wih[row * INSZ + k] : Whh[row * HID + (k - INSZ)];
        __nv_bfloat16 hi = __float2bfloat16(w);
        g_W2T_hi[idx] = hi;
        g_W2T_lo[idx] = __float2bfloat16(w - __bfloat162float(hi));
    } else if (idx < T2) {
        int n = idx - T1;
        int gate = n & 3, h = n >> 2;
        g_bias[n] = bih[gate * HID + h] + bhh[gate * HID + h];
    }
}

__global__ void reorder_fc_kernel(const float* __restrict__ Wfc) {
    int j = blockIdx.x * blockDim.x + threadIdx.x;
    if (j < HID * NC) {
        int h = j / NC, c = j % NC;
        g_Wfct[j] = Wfc[c * HID + h];
    }
}

// ---------------- one LSTM step: bf16x3 mma.sync GEMM + fused cell update ----------------
// grid (NG/TN=16, BATCH/TM=8) = 128 CTAs x 256 threads (8 warps).
// Warp w computes the full 32-row M x 16 gate-cols [w*16, w*16+16).
__global__ __launch_bounds__(256) void step_kernel(const float* __restrict__ x, int t) {
    __shared__ __align__(16) char sm[SM_BYTES];

    const int tid = threadIdx.x;
    const int lane = tid & 31;
    const int wid = tid >> 5;
    const int n0 = blockIdx.x * TN;
    const int m0 = blockIdx.y * TM;
    const int rb = t & 1, wb = rb ^ 1;

    __nv_bfloat16* const sAH = (__nv_bfloat16*)(sm);            // [2][32][APAD]
    __nv_bfloat16* const sAL = (__nv_bfloat16*)(sm + 3072);
    __nv_bfloat16* const sBH = (__nv_bfloat16*)(sm + 6144);     // [2][128][BPAD]
    __nv_bfloat16* const sBL = (__nv_bfloat16*)(sm + 18432);

    // loader roles
    const int arow = tid >> 3, acol = (tid & 7) * 2;     // A: 32 rows x 16 k, bf16x2 per thread
    const int brow = tid >> 1, bk8 = (tid & 1) * 8;      // B: 128 rows x 16 k, uint4 per thread

    const float* __restrict__ xr = &x[((size_t)(m0 + arow) * TT + t) * INSZ];
    const __nv_bfloat16* __restrict__ hhi = g_h_hi[rb] + (size_t)(m0 + arow) * HID;
    const __nv_bfloat16* __restrict__ hlo = g_h_lo[rb] + (size_t)(m0 + arow) * HID;
    const __nv_bfloat16* __restrict__ wh = g_W2T_hi + (size_t)(n0 + brow) * KTOT + bk8;
    const __nv_bfloat16* __restrict__ wl = g_W2T_lo + (size_t)(n0 + brow) * KTOT + bk8;

    // ldmatrix source addresses per buffer
    const int a_r = lane & 15, a_c8 = (lane >> 4) * 8;    // A quads: (rows, k-half)
    const int b_g = lane >> 3;                            // B quads: (nt, k-half)
    const int b_r = wid * 16 + (b_g >> 1) * 8 + (lane & 7);
    const int b_c8 = (b_g & 1) * 8;
    uint32_t aAH[2][2], aAL[2][2], aBH[2], aBL[2];
#pragma unroll
    for (int buf = 0; buf < 2; buf++) {
#pragma unroll
        for (int mt = 0; mt < 2; mt++) {
            int off = buf * 768 + (mt * 16 + a_r) * APAD + a_c8;
            aAH[buf][mt] = smem_u32(sAH + off);
            aAL[buf][mt] = smem_u32(sAL + off);
        }
        int boff = buf * 3072 + b_r * BPAD + b_c8;
        aBH[buf] = smem_u32(sBH + boff);
        aBL[buf] = smem_u32(sBL + boff);
    }

    float acc[2][2][4] = {};    // [mt][nt][reg]
    uint32_t sa_h, sa_l;
    uint4 sb_h, sb_l;

#define LOAD_STAGE(kc) do {                                                     \
    if ((kc) < INSZ) {                                                          \
        float2 v = *(const float2*)&xr[(kc) + acol];                            \
        __nv_bfloat16 h0 = __float2bfloat16(v.x);                               \
        __nv_bfloat16 h1 = __float2bfloat16(v.y);                               \
        __nv_bfloat16 l0 = __float2bfloat16(v.x - __bfloat162float(h0));        \
        __nv_bfloat16 l1 = __float2bfloat16(v.y - __bfloat162float(h1));        \
        sa_h = (uint32_t)__bfloat16_as_ushort(h0) | ((uint32_t)__bfloat16_as_ushort(h1) << 16); \
        sa_l = (uint32_t)__bfloat16_as_ushort(l0) | ((uint32_t)__bfloat16_as_ushort(l1) << 16); \
    } else {                                                                    \
        sa_h = *(const uint32_t*)&hhi[(kc) - INSZ + acol];                      \
        sa_l = *(const uint32_t*)&hlo[(kc) - INSZ + acol];                      \
    }                                                                           \
    sb_h = *(const uint4*)&wh[(kc)];                                            \
    sb_l = *(const uint4*)&wl[(kc)];                                            \
} while (0)

#define STORE_STAGE(buf) do {                                                   \
    *(uint32_t*)&sAH[(buf) * 768 + arow * APAD + acol] = sa_h;                  \
    *(uint32_t*)&sAL[(buf) * 768 + arow * APAD + acol] = sa_l;                  \
    *(uint4*)&sBH[(buf) * 3072 + brow * BPAD + bk8] = sb_h;                     \
    *(uint4*)&sBL[(buf) * 3072 + brow * BPAD + bk8] = sb_l;                     \
} while (0)

    LOAD_STAGE(0);
    STORE_STAGE(0);
    __syncthreads();

    for (int ch = 0; ch < NCHK; ch++) {
        const int buf = ch & 1;
        if (ch + 1 < NCHK) LOAD_STAGE((ch + 1) * 16);

        uint32_t ah[2][4], al[2][4], bh[4], bl[4];
        LDSM_X4(ah[0], aAH[buf][0]);
        LDSM_X4(ah[1], aAH[buf][1]);
        LDSM_X4(al[0], aAL[buf][0]);
        LDSM_X4(al[1], aAL[buf][1]);
        LDSM_X4(bh, aBH[buf]);   // {nt0.k0-7, nt0.k8-15, nt1.k0-7, nt1.k8-15}
        LDSM_X4(bl, aBL[buf]);

#pragma unroll
        for (int mt = 0; mt < 2; mt++)
#pragma unroll
            for (int nt = 0; nt < 2; nt++) {
                MMA_BF16(acc[mt][nt], ah[mt], &bh[nt * 2]);
                MMA_BF16(acc[mt][nt], ah[mt], &bl[nt * 2]);
                MMA_BF16(acc[mt][nt], al[mt], &bh[nt * 2]);
            }

        if (ch + 1 < NCHK) STORE_STAGE(buf ^ 1);
        __syncthreads();
    }

    // ---- epilogue: regroup gates via smem, then cell update ----
    float* gb = (float*)sm;                         // [32][132] fp32, reuses staging smem
    {
        const int r = lane >> 2;
        const int cb = wid * 16 + (lane & 3) * 2;
#pragma unroll
        for (int mt = 0; mt < 2; mt++)
#pragma unroll
            for (int nt = 0; nt < 2; nt++) {
                int row = mt * 16 + r;
                int col = cb + nt * 8;
                gb[row * 132 + col]           = acc[mt][nt][0];
                gb[row * 132 + col + 1]       = acc[mt][nt][1];
                gb[(row + 8) * 132 + col]     = acc[mt][nt][2];
                gb[(row + 8) * 132 + col + 1] = acc[mt][nt][3];
            }
    }
    __syncthreads();

    {
        const int uu = tid & 31;                     // local hidden unit 0..31
        const int r0 = (tid >> 5) * 4;               // 4 batch rows per thread
        const int gu = (n0 >> 2) + uu;               // global hidden unit
        const float4 bi = *(const float4*)&g_bias[n0 + uu * 4];
#pragma unroll
        for (int i = 0; i < 4; i++) {
            const int row = r0 + i;
            float4 gv = *(const float4*)&gb[row * 132 + uu * 4];
            float gi = gv.x + bi.x;
            float gf = gv.y + bi.y;
            float gg = gv.z + bi.z;
            float go = gv.w + bi.w;
            const int idx = (m0 + row) * HID + gu;
            float c = sigm_f(gf) * g_c[idx] + sigm_f(gi) * tanh_f(gg);
            g_c[idx] = c;
            float h = sigm_f(go) * tanh_f(c);
            g_hf[wb][idx] = h;
            __nv_bfloat16 hh = __float2bfloat16(h);
            g_h_hi[wb][idx] = hh;
            g_h_lo[wb][idx] = __float2bfloat16(h - __bfloat162float(hh));
        }
    }
#undef LOAD_STAGE
#undef STORE_STAGE
}

// ---------------- FC head ----------------
__global__ __launch_bounds__(128) void fc_kernel(const float* __restrict__ bfc, float* __restrict__ out) {
    __shared__ float hs[HID];
    const int b = blockIdx.x;
    for (int i = threadIdx.x; i < HID; i += blockDim.x)
        hs[i] = g_hf[0][b * HID + i];        // TT even -> last write lands in buffer 0
    __syncthreads();
    const int j = threadIdx.x;
    float s = bfc[j];
#pragma unroll 8
    for (int h = 0; h < HID; h++)
        s += hs[h] * g_Wfct[h * NC + j];
    out[b * NC + j] = s;
}

// ---------------- launch ----------------
extern "C" void kernel_launch(void* const* d_in, const int* in_sizes, int n_in,
                              void* d_out, int out_size) {
    const float* x   = (const float*)d_in[0];
    const float* Wih = (const float*)d_in[1];
    const float* Whh = (const float*)d_in[2];
    const float* bih = (const float*)d_in[3];
    const float* bhh = (const float*)d_in[4];
    const float* Wfc = (const float*)d_in[5];
    const float* bfc = (const float*)d_in[6];
    float* out = (float*)d_out;

    init_kernel<<<(BATCH * HID + 255) / 256, 256>>>();

    const int reorder_total = NG * KTOT + NG;
    reorder_kernel<<<(reorder_total + 255) / 256, 256>>>(Wih, Whh, bih, bhh);
    reorder_fc_kernel<<<(HID * NC + 255) / 256, 256>>>(Wfc);

    dim3 gs(NG / TN, BATCH / TM);   // (16, 8) = 128 CTAs
    for (int t = 0; t < TT; t++)
        step_kernel<<<gs, 256>>>(x, t);

    fc_kernel<<<BATCH, NC>>>(bfc, out);
}

// round 17
// speedup vs baseline: 3.0395x; 1.2536x over previous
#include <cuda_runtime.h>
#include <cuda_bf16.h>
#include <cstdint>

#define BATCH 256
#define TT    512
#define INSZ  256
#define HID   512
#define NG    2048          // 4*HID, gate-interleaved: n = h*4 + gate (0=i,1=f,2=g,3=o)
#define KTOT  768           // INSZ + HID
#define NC    128

#define TM    32            // batch rows per CTA
#define TN    64            // gate cols per CTA (16 hidden units)
#define NCHK  48            // KTOT/16
#define NSTAGE 3
#define STAGE_B 9216        // AH 1536 | AL 1536 | BH 3072 | BL 3072
#define SM_BYTES (NSTAGE * STAGE_B)   // 27648

// ---------------- device scratch (~8 MB) ----------------
__device__ __nv_bfloat16 g_W2T_hi[NG * KTOT];     // [n][k] n-major
__device__ __nv_bfloat16 g_W2T_lo[NG * KTOT];
__device__ float         g_bias[NG];
__device__ float         g_Wfct[HID * NC];
__device__ __nv_bfloat16 g_h_hi[2][BATCH * HID];
__device__ __nv_bfloat16 g_h_lo[2][BATCH * HID];
__device__ float         g_hf[2][BATCH * HID];
__device__ float         g_c[BATCH * HID];

// ---------------- helpers ----------------
__device__ __forceinline__ uint32_t smem_u32(const void* p) {
    uint32_t a;
    asm("{ .reg .u64 t; cvta.to.shared.u64 t, %1; cvt.u32.u64 %0, t; }" : "=r"(a) : "l"(p));
    return a;
}
__device__ __forceinline__ float sigm_f(float x) { return 1.f / (1.f + __expf(-x)); }
__device__ __forceinline__ float tanh_f(float x) { return 1.f - 2.f / (__expf(2.f * x) + 1.f); }

#define LDSM_X4(r, addr) \
    asm volatile("ldmatrix.sync.aligned.m8n8.x4.shared.b16 {%0,%1,%2,%3}, [%4];" \
        : "=r"((r)[0]), "=r"((r)[1]), "=r"((r)[2]), "=r"((r)[3]) : "r"(addr))

#define MMA_BF16(d, a, b) \
    asm volatile("mma.sync.aligned.m16n8k16.row.col.f32.bf16.bf16.f32 " \
        "{%0,%1,%2,%3}, {%4,%5,%6,%7}, {%8,%9}, {%0,%1,%2,%3};" \
        : "+f"((d)[0]), "+f"((d)[1]), "+f"((d)[2]), "+f"((d)[3]) \
        : "r"((a)[0]), "r"((a)[1]), "r"((a)[2]), "r"((a)[3]), "r"((b)[0]), "r"((b)[1]))

#define CP16(dst, src) \
    asm volatile("cp.async.cg.shared.global [%0], [%1], 16;" :: "r"(dst), "l"(src) : "memory")
#define CP_COMMIT() asm volatile("cp.async.commit_group;" ::: "memory")
#define CP_WAIT1()  asm volatile("cp.async.wait_group 1;" ::: "memory")

// ---------------- init ----------------
__global__ void init_kernel() {
    int i = blockIdx.x * blockDim.x + threadIdx.x;
    if (i < BATCH * HID) {
        g_h_hi[0][i] = __float2bfloat16(0.f);
        g_h_lo[0][i] = __float2bfloat16(0.f);
        g_c[i] = 0.f;
    }
}

// ---------------- weight reorder: [n][k] n-major bf16 hi/lo + bias ----------------
__global__ void reorder_kernel(const float* __restrict__ Wih, const float* __restrict__ Whh,
                               const float* __restrict__ bih, const float* __restrict__ bhh) {
    int idx = blockIdx.x * blockDim.x + threadIdx.x;
    const int T1 = NG * KTOT;
    const int T2 = T1 + NG;
    if (idx < T1) {
        int n = idx / KTOT, k = idx % KTOT;
        int gate = n & 3, h = n >> 2;
        int row = gate * HID + h;
        float w = (k < INSZ) ? Wih[row * INSZ + k] : Whh[row * HID + (k - INSZ)];
        __nv_bfloat16 hi = __float2bfloat16(w);
        g_W2T_hi[idx] = hi;
        g_W2T_lo[idx] = __float2bfloat16(w - __bfloat162float(hi));
    } else if (idx < T2) {
        int n = idx - T1;
        int gate = n & 3, h = n >> 2;
        g_bias[n] = bih[gate * HID + h] + bhh[gate * HID + h];
    }
}

__global__ void reorder_fc_kernel(const float* __restrict__ Wfc) {
    int j = blockIdx.x * blockDim.x + threadIdx.x;
    if (j < HID * NC) {
        int h = j / NC, c = j % NC;
        g_Wfct[j] = Wfc[c * HID + h];
    }
}

// ---------------- one LSTM step: bf16x3 mma.sync + cp.async 3-stage pipeline ----------------
// grid (NG/TN=32, BATCH/TM=8) = 256 CTAs x 128 threads (4 warps).
// Warp w computes 32 rows x 16 gate-cols [w*16, w*16+16).
__global__ __launch_bounds__(128) void step_kernel(const float* __restrict__ x, int t) {
    __shared__ __align__(16) char sm[SM_BYTES];

    const int tid = threadIdx.x;
    const int lane = tid & 31;
    const int wid = tid >> 5;
    const int n0 = blockIdx.x * TN;
    const int m0 = blockIdx.y * TM;
    const int rb = t & 1, wb = rb ^ 1;
    const uint32_t smb = smem_u32(sm);

    // ---- A loader: 32 rows x 16 k x {hi,lo}; one 16B op per thread ----
    const int a_row = tid >> 2, a_sel = tid & 3;
    const int a_half = a_sel & 1, a_hl = a_sel >> 1;
    const uint32_t a_doff = (uint32_t)(a_hl * 1536 + a_row * 48 + a_half * 16);
    const float* __restrict__ xrow_p = x + ((size_t)(m0 + a_row) * TT + t) * INSZ + a_half * 8;
    const __nv_bfloat16* __restrict__ ah_src =
        (a_hl ? g_h_lo[rb] : g_h_hi[rb]) + (size_t)(m0 + a_row) * HID + a_half * 8;

    // ---- B loader: 64 rows x 16 k x {hi,lo}; two 16B ops per thread ----
    const int b_row = tid >> 1, b_hl = tid & 1;
    const uint32_t b_doff = (uint32_t)(3072 + b_hl * 3072 + b_row * 48);
    const __nv_bfloat16* __restrict__ b_srcb =
        (b_hl ? g_W2T_lo : g_W2T_hi) + (size_t)(n0 + b_row) * KTOT;

    // ---- ldmatrix addresses per stage (constant-indexed; loop unrolled x3) ----
    const int a_r = lane & 15, a_c16 = (lane >> 4) * 16;
    const int b_g = lane >> 3;
    const int b_rr = wid * 16 + ((b_g >> 1) << 3) + (lane & 7);
    const int b_c16 = (b_g & 1) * 16;
    uint32_t adrH[NSTAGE][2], adrL[NSTAGE][2], bdrH[NSTAGE], bdrL[NSTAGE];
#pragma unroll
    for (int s = 0; s < NSTAGE; s++) {
#pragma unroll
        for (int mt = 0; mt < 2; mt++) {
            uint32_t o = s * STAGE_B + (mt * 16 + a_r) * 48 + a_c16;
            adrH[s][mt] = smb + o;
            adrL[s][mt] = smb + o + 1536;
        }
        uint32_t bo = s * STAGE_B + 3072 + b_rr * 48 + b_c16;
        bdrH[s] = smb + bo;
        bdrL[s] = smb + bo + 3072;
    }

    float acc[2][2][4] = {};

#define ISSUE(s, kc) do {                                                          \
    uint32_t _ab = smb + (s) * STAGE_B + a_doff;                                   \
    if ((kc) >= INSZ) {                                                            \
        CP16(_ab, ah_src + ((kc) - INSZ));                                         \
    } else {                                                                       \
        float vv[8];                                                               \
        *(float4*)&vv[0] = *(const float4*)(xrow_p + (kc));                        \
        *(float4*)&vv[4] = *(const float4*)(xrow_p + (kc) + 4);                    \
        unsigned short u8[8];                                                      \
        _Pragma("unroll")                                                          \
        for (int j = 0; j < 8; j++) {                                              \
            __nv_bfloat16 hb = __float2bfloat16(vv[j]);                            \
            u8[j] = a_hl ? __bfloat16_as_ushort(__float2bfloat16(vv[j] - __bfloat162float(hb))) \
                         : __bfloat16_as_ushort(hb);                               \
        }                                                                          \
        *(uint4*)(sm + (_ab - smb)) = *(uint4*)u8;                                 \
    }                                                                              \
    uint32_t _bb = smb + (s) * STAGE_B + b_doff;                                   \
    CP16(_bb,      b_srcb + (kc));                                                 \
    CP16(_bb + 16, b_srcb + (kc) + 8);                                             \
} while (0)

#define COMPUTE(s) do {                                                            \
    uint32_t ah0[4], ah1[4], al0[4], al1[4], bh[4], bl[4];                         \
    LDSM_X4(ah0, adrH[s][0]); LDSM_X4(ah1, adrH[s][1]);                            \
    LDSM_X4(al0, adrL[s][0]); LDSM_X4(al1, adrL[s][1]);                            \
    LDSM_X4(bh, bdrH[s]);     LDSM_X4(bl, bdrL[s]);                                \
    MMA_BF16(acc[0][0], ah0, &bh[0]); MMA_BF16(acc[0][1], ah0, &bh[2]);            \
    MMA_BF16(acc[1][0], ah1, &bh[0]); MMA_BF16(acc[1][1], ah1, &bh[2]);            \
    MMA_BF16(acc[0][0], ah0, &bl[0]); MMA_BF16(acc[0][1], ah0, &bl[2]);            \
    MMA_BF16(acc[1][0], ah1, &bl[0]); MMA_BF16(acc[1][1], ah1, &bl[2]);            \
    MMA_BF16(acc[0][0], al0, &bh[0]); MMA_BF16(acc[0][1], al0, &bh[2]);            \
    MMA_BF16(acc[1][0], al1, &bh[0]); MMA_BF16(acc[1][1], al1, &bh[2]);            \
} while (0)

    // prologue: chunks 0,1 into stages 0,1
    ISSUE(0, 0);  CP_COMMIT();
    ISSUE(1, 16); CP_COMMIT();

    for (int chb = 0; chb < NCHK; chb += 3) {
        // ch = chb, stage 0
        CP_WAIT1(); __syncthreads();
        if (chb + 2 < NCHK) ISSUE(2, (chb + 2) * 16);
        CP_COMMIT();
        COMPUTE(0);
        // ch = chb+1, stage 1
        CP_WAIT1(); __syncthreads();
        if (chb + 3 < NCHK) ISSUE(0, (chb + 3) * 16);
        CP_COMMIT();
        COMPUTE(1);
        // ch = chb+2, stage 2
        CP_WAIT1(); __syncthreads();
        if (chb + 4 < NCHK) ISSUE(1, (chb + 4) * 16);
        CP_COMMIT();
        COMPUTE(2);
    }
    __syncthreads();

#undef ISSUE
#undef COMPUTE

    // ---- epilogue: regroup gates via smem, then cell update ----
    float* gb = (float*)sm;                          // [32][68] fp32
    {
        const int r = lane >> 2;
        const int cb = wid * 16 + (lane & 3) * 2;
#pragma unroll
        for (int mt = 0; mt < 2; mt++)
#pragma unroll
            for (int nt = 0; nt < 2; nt++) {
                int row = mt * 16 + r;
                int col = cb + nt * 8;
                gb[row * 68 + col]           = acc[mt][nt][0];
                gb[row * 68 + col + 1]       = acc[mt][nt][1];
                gb[(row + 8) * 68 + col]     = acc[mt][nt][2];
                gb[(row + 8) * 68 + col + 1] = acc[mt][nt][3];
            }
    }
    __syncthreads();

    {
        const int uu = tid & 15;                     // local hidden unit 0..15
        const int r0 = (tid >> 4) * 4;               // 4 batch rows per thread
        const int gu = (n0 >> 2) + uu;               // global hidden unit
        const float4 bi = *(const float4*)&g_bias[n0 + uu * 4];
#pragma unroll
        for (int i = 0; i < 4; i++) {
            const int row = r0 + i;
            float4 gv = *(const float4*)&gb[row * 68 + uu * 4];
            float gi = gv.x + bi.x;
            float gf = gv.y + bi.y;
            float gg = gv.z + bi.z;
            float go = gv.w + bi.w;
            const int idx = (m0 + row) * HID + gu;
            float c = sigm_f(gf) * g_c[idx] + sigm_f(gi) * tanh_f(gg);
            g_c[idx] = c;
            float h = sigm_f(go) * tanh_f(c);
            g_hf[wb][idx] = h;
            __nv_bfloat16 hh = __float2bfloat16(h);
            g_h_hi[wb][idx] = hh;
            g_h_lo[wb][idx] = __float2bfloat16(h - __bfloat162float(hh));
        }
    }
}

// ---------------- FC head ----------------
__global__ __launch_bounds__(128) void fc_kernel(const float* __restrict__ bfc, float* __restrict__ out) {
    __shared__ float hs[HID];
    const int b = blockIdx.x;
    for (int i = threadIdx.x; i < HID; i += blockDim.x)
        hs[i] = g_hf[0][b * HID + i];        // TT even -> last write lands in buffer 0
    __syncthreads();
    const int j = threadIdx.x;
    float s = bfc[j];
#pragma unroll 8
    for (int h = 0; h < HID; h++)
        s += hs[h] * g_Wfct[h * NC + j];
    out[b * NC + j] = s;
}

// ---------------- launch ----------------
extern "C" void kernel_launch(void* const* d_in, const int* in_sizes, int n_in,
                              void* d_out, int out_size) {
    const float* x   = (const float*)d_in[0];
    const float* Wih = (const float*)d_in[1];
    const float* Whh = (const float*)d_in[2];
    const float* bih = (const float*)d_in[3];
    const float* bhh = (const float*)d_in[4];
    const float* Wfc = (const float*)d_in[5];
    const float* bfc = (const float*)d_in[6];
    float* out = (float*)d_out;

    init_kernel<<<(BATCH * HID + 255) / 256, 256>>>();

    const int reorder_total = NG * KTOT + NG;
    reorder_kernel<<<(reorder_total + 255) / 256, 256>>>(Wih, Whh, bih, bhh);
    reorder_fc_kernel<<<(HID * NC + 255) / 256, 256>>>(Wfc);

    dim3 gs(NG / TN, BATCH / TM);   // (32, 8) = 256 CTAs
    for (int t = 0; t < TT; t++)
        step_kernel<<<gs, 128>>>(x, t);

    fc_kernel<<<BATCH, NC>>>(bfc, out);
}